// round 13
// baseline (speedup 1.0000x reference)
#include <cuda_runtime.h>
#include <cuda_fp16.h>
#include <math.h>
#include <stdint.h>

// Problem constants
#define LSEQ   512
#define BATCH  32
#define NIN    72
#define DDIM   512
#define NOUTC  144
#define NLAYER 5
#define MROWS  (LSEQ*BATCH)   // 16384
#define D2     (2*DDIM)       // 1024

// Scratch (device globals — no allocation allowed)
__device__ float  g_y [MROWS*D2];      // layer ping (fp32 h)
__device__ float  g_h [MROWS*D2];      // layer pong (fp32 h)
__device__ __half g_xth[MROWS*D2];     // LN output fp16 (GEMM A + scan residual)
__device__ __half g_U [MROWS*4*D2];    // GEMM output U, fp16
__device__ __align__(16) __half g_zero8[8] = {};
#define WT_W0_ELEMS (DDIM*4*D2)
#define WT_WL_ELEMS ((NLAYER-1)*D2*3*D2)
#define WT_L2_ELEMS (D2*NOUTC)
__device__ __half g_wth[WT_W0_ELEMS + WT_WL_ELEMS + WT_L2_ELEMS];

// ---------------------------------------------------------------------------
// Helpers
// ---------------------------------------------------------------------------
__device__ __forceinline__ uint32_t smem_u32(const void* p) {
    uint32_t a;
    asm("{ .reg .u64 t; cvta.to.shared.u64 t, %1; cvt.u32.u64 %0, t; }"
        : "=r"(a) : "l"(p));
    return a;
}
__device__ __forceinline__ uint32_t pack_h2(float a, float b) {
    __half2 h = __floats2half2_rn(a, b);
    return *(uint32_t*)&h;
}
__device__ __forceinline__ void cp16(uint32_t s, const void* g) {
    asm volatile("cp.async.cg.shared.global [%0], [%1], 16;" :: "r"(s), "l"(g));
}
// Fast sigmoid: MUFU ex2 + rcp (rel err ~2^-22)
__device__ __forceinline__ float sigmf(float x) {
    float e;
    asm("ex2.approx.ftz.f32 %0, %1;" : "=f"(e) : "f"(-1.44269504f * x));
    float r;
    asm("rcp.approx.ftz.f32 %0, %1;" : "=f"(r) : "f"(1.f + e));
    return r;
}
#define LDSM_X4(r0,r1,r2,r3,addr) \
    asm volatile("ldmatrix.sync.aligned.m8n8.x4.shared.b16 {%0,%1,%2,%3}, [%4];" \
        : "=r"(r0), "=r"(r1), "=r"(r2), "=r"(r3) : "r"(addr))
#define LDSM_X4T(r0,r1,r2,r3,addr) \
    asm volatile("ldmatrix.sync.aligned.m8n8.x4.trans.shared.b16 {%0,%1,%2,%3}, [%4];" \
        : "=r"(r0), "=r"(r1), "=r"(r2), "=r"(r3) : "r"(addr))

// ---------------------------------------------------------------------------
// Round fp32 -> fp16 (vectorized)
// ---------------------------------------------------------------------------
__global__ __launch_bounds__(256) void round_f16_kernel(
    const float4* __restrict__ in, uint2* __restrict__ out, int n4)
{
    int i = blockIdx.x * blockDim.x + threadIdx.x;
    if (i < n4) {
        float4 v = in[i];
        uint2 t;
        t.x = pack_h2(v.x, v.y);
        t.y = pack_h2(v.z, v.w);
        out[i] = t;
    }
}

// ---------------------------------------------------------------------------
// FP16 tensor-core GEMM — round-11 validated config, FROZEN mainloop.
// 128x128 CTA tile, BK=32, 128 threads (4 warps, 2x2 grid of 64x64 warp
// tiles), 3-stage cp.async, compute-then-prefetch order, 2 CTAs/SM.
// OUTH: store C as fp16 (U path). GUARD/HASBIAS: lin2 epilogue only.
// ---------------------------------------------------------------------------
#define TBM 128
#define TBN 128
#define TBK 32
#define ASTR 40
#define BSTR 136
#define ABYT (TBM*ASTR*2)            // 10240
#define BBYT (TBK*BSTR*2)            // 8704
#define STG  (ABYT+BBYT)             // 18944
#define TSMEM (3*STG)                // 56832

template<bool GUARD, bool HASBIAS, bool OUTH>
__global__ __launch_bounds__(128) void gemm_f16_kernel(
    const __half* __restrict__ A, const __half* __restrict__ B,
    const float* __restrict__ bias, void* __restrict__ Cv,
    int N, int K)
{
    extern __shared__ char smem[];
    const uint32_t sb = smem_u32(smem);
    const int tid  = threadIdx.x;
    const int w    = tid >> 5;
    const int lane = tid & 31;
    const int wm   = w & 1;
    const int wn   = w >> 1;
    const int bm   = blockIdx.y * TBM;
    const int bn   = blockIdx.x * TBN;
    const int l15  = lane & 15;
    const int lhi  = lane >> 4;

    float acc[4][8][4];
    #pragma unroll
    for (int i = 0; i < 4; i++)
        #pragma unroll
        for (int j = 0; j < 8; j++)
            #pragma unroll
            for (int r = 0; r < 4; r++) acc[i][j][r] = 0.f;

    const int nc = K / TBK;

    auto load_chunk = [&](int ch, int s) {
        const int k0 = ch * TBK;
        const uint32_t sA = sb + s * STG;
        const uint32_t sB = sA + ABYT;
        #pragma unroll
        for (int i = 0; i < 4; i++) {
            int idx = tid + i * 128;
            int row = idx >> 2, q = idx & 3;
            cp16(sA + (row * ASTR + q * 8) * 2,
                 A + (size_t)(bm + row) * K + k0 + q * 8);
        }
        #pragma unroll
        for (int i = 0; i < 4; i++) {
            int idx = tid + i * 128;
            int row = idx >> 4, q = idx & 15;
            if (GUARD) {
                int gc = bn + q * 8;
                const void* src = (gc < N)
                    ? (const void*)(B + (size_t)(k0 + row) * N + gc)
                    : (const void*)g_zero8;
                cp16(sB + (row * BSTR + q * 8) * 2, src);
            } else {
                cp16(sB + (row * BSTR + q * 8) * 2,
                     B + (size_t)(k0 + row) * N + bn + q * 8);
            }
        }
    };

    uint32_t aoff[4], boff[4];
    #pragma unroll
    for (int mi = 0; mi < 4; mi++)
        aoff[mi] = ((wm * 64 + mi * 16 + l15) * ASTR + lhi * 8) * 2;
    #pragma unroll
    for (int nj = 0; nj < 4; nj++)
        boff[nj] = (l15 * BSTR + wn * 64 + nj * 16 + lhi * 8) * 2;

    load_chunk(0, 0);
    asm volatile("cp.async.commit_group;" ::: "memory");
    if (nc > 1) load_chunk(1, 1);
    asm volatile("cp.async.commit_group;" ::: "memory");

    for (int ch = 0; ch < nc; ch++) {
        const int s = ch % 3;
        asm volatile("cp.async.wait_group 1;" ::: "memory");
        __syncthreads();

        const uint32_t sA = sb + s * STG;
        const uint32_t sB = sA + ABYT;
        #pragma unroll
        for (int kk = 0; kk < 2; kk++) {
            uint32_t af[4][4], bf[8][2];
            #pragma unroll
            for (int mi = 0; mi < 4; mi++)
                LDSM_X4(af[mi][0], af[mi][1], af[mi][2], af[mi][3],
                        sA + aoff[mi] + kk * 32);
            #pragma unroll
            for (int nj = 0; nj < 4; nj++)
                LDSM_X4T(bf[2*nj][0], bf[2*nj][1], bf[2*nj+1][0], bf[2*nj+1][1],
                         sB + boff[nj] + kk * 16 * BSTR * 2);
            #pragma unroll
            for (int mi = 0; mi < 4; mi++)
                #pragma unroll
                for (int ni = 0; ni < 8; ni++) {
                    asm volatile(
                        "mma.sync.aligned.m16n8k16.row.col.f32.f16.f16.f32 "
                        "{%0,%1,%2,%3}, {%4,%5,%6,%7}, {%8,%9}, {%0,%1,%2,%3};"
                        : "+f"(acc[mi][ni][0]), "+f"(acc[mi][ni][1]),
                          "+f"(acc[mi][ni][2]), "+f"(acc[mi][ni][3])
                        : "r"(af[mi][0]), "r"(af[mi][1]),
                          "r"(af[mi][2]), "r"(af[mi][3]),
                          "r"(bf[ni][0]), "r"(bf[ni][1]));
                }
        }

        if (ch + 2 < nc) load_chunk(ch + 2, (ch + 2) % 3);
        asm volatile("cp.async.commit_group;" ::: "memory");
    }

    // Epilogue
    #pragma unroll
    for (int mi = 0; mi < 4; mi++) {
        const size_t r0 = (size_t)bm + wm * 64 + mi * 16 + (lane >> 2);
        #pragma unroll
        for (int ni = 0; ni < 8; ni++) {
            const int colblk = bn + wn * 64 + ni * 8;
            if (GUARD && colblk >= N) continue;
            const int col = colblk + (lane & 3) * 2;
            float v0 = acc[mi][ni][0], v1 = acc[mi][ni][1];
            float v2 = acc[mi][ni][2], v3 = acc[mi][ni][3];
            if (HASBIAS) {
                float b0 = bias[col], b1 = bias[col + 1];
                v0 += b0; v1 += b1; v2 += b0; v3 += b1;
            }
            if (OUTH) {
                __half* Ch = (__half*)Cv;
                *(__half2*)(Ch + r0 * N + col)       = __floats2half2_rn(v0, v1);
                *(__half2*)(Ch + (r0 + 8) * N + col) = __floats2half2_rn(v2, v3);
            } else {
                float* C = (float*)Cv;
                *(float2*)(C + r0 * N + col)       = make_float2(v0, v1);
                *(float2*)(C + (r0 + 8) * N + col) = make_float2(v2, v3);
            }
        }
    }
}

// ---------------------------------------------------------------------------
// Classic SGEMM (lin1 only: K=72, exact fp32 to preserve error margin)
// ---------------------------------------------------------------------------
#define BM 128
#define BN 128
#define BK 8

__global__ __launch_bounds__(256) void sgemm_kernel(
    const float* __restrict__ A, const float* __restrict__ B,
    const float* __restrict__ bias, float* __restrict__ C,
    int M, int N, int K, int relu)
{
    __shared__ float As[BK][BM];
    __shared__ float Bs[BK][BN];

    const int tid = threadIdx.x;
    const int bm  = blockIdx.y * BM;
    const int bn  = blockIdx.x * BN;
    const int tx  = tid & 15;
    const int ty  = tid >> 4;

    const int arow = tid >> 1;
    const int acol = (tid & 1) * 4;
    const int brow = tid >> 5;
    const int bcol = (tid & 31) * 4;

    float acc[8][8];
    #pragma unroll
    for (int i = 0; i < 8; i++)
        #pragma unroll
        for (int j = 0; j < 8; j++) acc[i][j] = 0.f;

    for (int k0 = 0; k0 < K; k0 += BK) {
        float4 av = *(const float4*)(A + (size_t)(bm + arow) * K + k0 + acol);
        As[acol + 0][arow] = av.x;
        As[acol + 1][arow] = av.y;
        As[acol + 2][arow] = av.z;
        As[acol + 3][arow] = av.w;

        float4 bv = make_float4(0.f, 0.f, 0.f, 0.f);
        int gc = bn + bcol;
        const float* bp = B + (size_t)(k0 + brow) * N;
        if (gc + 3 < N) {
            bv = *(const float4*)(bp + gc);
        } else {
            if (gc     < N) bv.x = bp[gc];
            if (gc + 1 < N) bv.y = bp[gc + 1];
            if (gc + 2 < N) bv.z = bp[gc + 2];
            if (gc + 3 < N) bv.w = bp[gc + 3];
        }
        *(float4*)&Bs[brow][bcol] = bv;

        __syncthreads();

        #pragma unroll
        for (int kk = 0; kk < BK; kk++) {
            float ar[8], br[8];
            *(float4*)&ar[0] = *(const float4*)&As[kk][ty * 8];
            *(float4*)&ar[4] = *(const float4*)&As[kk][ty * 8 + 4];
            *(float4*)&br[0] = *(const float4*)&Bs[kk][tx * 8];
            *(float4*)&br[4] = *(const float4*)&Bs[kk][tx * 8 + 4];
            #pragma unroll
            for (int i = 0; i < 8; i++)
                #pragma unroll
                for (int j = 0; j < 8; j++)
                    acc[i][j] += ar[i] * br[j];
        }
        __syncthreads();
    }

    #pragma unroll
    for (int i = 0; i < 8; i++) {
        int row = bm + ty * 8 + i;
        #pragma unroll
        for (int j = 0; j < 8; j++) {
            int col = bn + tx * 8 + j;
            if (col < N) {
                float v = acc[i][j];
                if (bias) v += bias[col];
                if (relu) v = fmaxf(v, 0.f);
                C[(size_t)row * N + col] = v;
            }
        }
    }
}

// ---------------------------------------------------------------------------
// One-pass LayerNorm -> fp16 only (feeds GEMM A and the scan residual).
// ---------------------------------------------------------------------------
template<int NV4>
__global__ __launch_bounds__(128) void ln_kernel(
    const float4* __restrict__ in, const float4* __restrict__ gw,
    const float4* __restrict__ bw, uint2* __restrict__ outh)
{
    const int W4  = NV4 * 128;
    const int row = blockIdx.x;
    const int tid = threadIdx.x;

    float4 v[NV4];
    #pragma unroll
    for (int i = 0; i < NV4; i++)
        v[i] = in[(size_t)row * W4 + tid + i * 128];

    float s = 0.f, s2 = 0.f;
    #pragma unroll
    for (int i = 0; i < NV4; i++) {
        s  += v[i].x + v[i].y + v[i].z + v[i].w;
        s2 += v[i].x * v[i].x + v[i].y * v[i].y
            + v[i].z * v[i].z + v[i].w * v[i].w;
    }

    __shared__ float sh0[4], sh1[4];
    #pragma unroll
    for (int o = 16; o; o >>= 1) {
        s  += __shfl_xor_sync(0xFFFFFFFFu, s,  o);
        s2 += __shfl_xor_sync(0xFFFFFFFFu, s2, o);
    }
    const int wq = tid >> 5, ln = tid & 31;
    if (ln == 0) { sh0[wq] = s; sh1[wq] = s2; }
    __syncthreads();
    s  = sh0[0] + sh0[1] + sh0[2] + sh0[3];
    s2 = sh1[0] + sh1[1] + sh1[2] + sh1[3];

    const float Wf   = (float)(NV4 * 512);
    const float mean = s / Wf;
    const float var  = s2 / Wf - mean * mean;
    const float inv  = rsqrtf(var + 1e-5f);

    #pragma unroll
    for (int i = 0; i < NV4; i++) {
        float4 g = gw[tid + i * 128];
        float4 b = bw[tid + i * 128];
        float4 o;
        o.x = (v[i].x - mean) * inv * g.x + b.x;
        o.y = (v[i].y - mean) * inv * g.y + b.y;
        o.z = (v[i].z - mean) * inv * g.z + b.z;
        o.w = (v[i].w - mean) * inv * g.w + b.w;
        uint2 t;
        t.x = pack_h2(o.x, o.y);
        t.y = pack_h2(o.z, o.w);
        outh[(size_t)row * W4 + tid + i * 128] = t;
    }
}

// ---------------------------------------------------------------------------
// Bidirectional SRU scan over fp16 U, 8-deep register prefetch, fast sigmoid.
// k=3 residual from fp16 LN output xh. h -> fp32 (mid layers) or fp16 into
// hh (last layer; feeds lin2; in-place over xh is safe: per-thread column,
// reads run 8 steps ahead of writes). c_out exact fp32.
// ---------------------------------------------------------------------------
__global__ __launch_bounds__(128) void sru_scan_kernel(
    const __half* __restrict__ U, const __half* __restrict__ xh,
    const float* __restrict__ wc, const float* __restrict__ bb,
    float* __restrict__ h, __half* __restrict__ hh,
    float* __restrict__ c_out, int k)
{
    const int idx = blockIdx.x * blockDim.x + threadIdx.x;
    const int d   = idx % DDIM;
    const int b   = (idx / DDIM) % BATCH;
    const int dir = idx / (BATCH * DDIM);

    const float wcf = wc[(0 * 2 + dir) * DDIM + d];
    const float wcr = wc[(1 * 2 + dir) * DDIM + d];
    const float bf  = bb[(0 * 2 + dir) * DDIM + d];
    const float br  = bb[(1 * 2 + dir) * DDIM + d];

    const int hcol = dir * DDIM + d;
    const int t0   = dir ? (LSEQ - 1) : 0;
    float c = 0.f;

    if (k == 4) {
        const uint2* U2 = (const uint2*)U;   // 4 halfs per (dir,d)
        const long long base = ((long long)t0 * BATCH + b) * D2 + hcol;
        const long long st   = dir ? -(long long)(BATCH * D2) : (long long)(BATCH * D2);
        long long ih = base;

        uint2 buf[8];
        #pragma unroll
        for (int j = 0; j < 8; j++) buf[j] = __ldcs(U2 + base + j * st);

        for (int s = 0; s < LSEQ; s += 8) {
            #pragma unroll
            for (int j = 0; j < 8; j++) {
                uint2 v = buf[j];
                if (s + 8 + j < LSEQ)
                    buf[j] = __ldcs(U2 + base + (long long)(s + 8 + j) * st);
                float2 f01 = __half22float2(*(__half2*)&v.x);
                float2 f23 = __half22float2(*(__half2*)&v.y);
                float f = sigmf(f01.y + wcf * c + bf);
                c = f * c + (1.f - f) * f01.x;
                float r = sigmf(f23.x + wcr * c + br);
                float hv = r * c + (1.f - r) * f23.y;
                if (hh) hh[ih] = __float2half_rn(hv);
                else    h[ih]  = hv;
                ih += st;
            }
        }
    } else {
        const long long baseu = ((long long)t0 * BATCH + b) * (3 * D2) + hcol * 3;
        const long long su    = dir ? -(long long)(BATCH * 3 * D2) : (long long)(BATCH * 3 * D2);
        const long long basex = ((long long)t0 * BATCH + b) * D2 + hcol;
        const long long sx    = dir ? -(long long)(BATCH * D2) : (long long)(BATCH * D2);

        float b0a[8], b1a[8], b2a[8], bra[8];
        #pragma unroll
        for (int j = 0; j < 8; j++) {
            const __half* up = U + baseu + j * su;
            b0a[j] = __half2float(__ldcs(up));
            b1a[j] = __half2float(__ldcs(up + 1));
            b2a[j] = __half2float(__ldcs(up + 2));
            bra[j] = __half2float(__ldcs(xh + basex + j * sx));
        }

        long long ih = basex;
        for (int s = 0; s < LSEQ; s += 8) {
            #pragma unroll
            for (int j = 0; j < 8; j++) {
                float u0 = b0a[j], u1 = b1a[j], u2 = b2a[j], res = bra[j];
                if (s + 8 + j < LSEQ) {
                    const __half* up = U + baseu + (long long)(s + 8 + j) * su;
                    b0a[j] = __half2float(__ldcs(up));
                    b1a[j] = __half2float(__ldcs(up + 1));
                    b2a[j] = __half2float(__ldcs(up + 2));
                    bra[j] = __half2float(__ldcs(xh + basex + (long long)(s + 8 + j) * sx));
                }
                float f = sigmf(u1 + wcf * c + bf);
                c = f * c + (1.f - f) * u0;
                float r = sigmf(u2 + wcr * c + br);
                float hv = r * c + (1.f - r) * res;
                if (hh) hh[ih] = __float2half_rn(hv);
                else    h[ih]  = hv;
                ih += sx;
            }
        }
    }
    c_out[(size_t)b * D2 + hcol] = c;
}

// ---------------------------------------------------------------------------
// Launch
// ---------------------------------------------------------------------------
extern "C" void kernel_launch(void* const* d_in, const int* in_sizes, int n_in,
                              void* d_out, int out_size)
{
    const float* x      = (const float*)d_in[0];
    const float* lin1_w = (const float*)d_in[1];
    const float* lin1_b = (const float*)d_in[2];
    const float* lin2_w = (const float*)d_in[3];
    const float* lin2_b = (const float*)d_in[4];
    const float* W0     = (const float*)d_in[5];
    const float* wc0    = (const float*)d_in[6];
    const float* b0     = (const float*)d_in[7];
    const float* ln0_g  = (const float*)d_in[8];
    const float* ln0_b  = (const float*)d_in[9];
    const float* Wl     = (const float*)d_in[10];
    const float* wcl    = (const float*)d_in[11];
    const float* bl     = (const float*)d_in[12];
    const float* lnl_g  = (const float*)d_in[13];
    const float* lnl_b  = (const float*)d_in[14];
    float* out = (float*)d_out;

    float *py, *ph;
    __half *pxth, *pU, *pwth;
    cudaGetSymbolAddress((void**)&py,   g_y);
    cudaGetSymbolAddress((void**)&ph,   g_h);
    cudaGetSymbolAddress((void**)&pxth, g_xth);
    cudaGetSymbolAddress((void**)&pU,   g_U);
    cudaGetSymbolAddress((void**)&pwth, g_wth);

    __half* pw_l2 = pwth + WT_W0_ELEMS + WT_WL_ELEMS;

    cudaFuncSetAttribute((const void*)gemm_f16_kernel<false, false, true>,
                         cudaFuncAttributeMaxDynamicSharedMemorySize, TSMEM);
    cudaFuncSetAttribute((const void*)gemm_f16_kernel<true, true, false>,
                         cudaFuncAttributeMaxDynamicSharedMemorySize, TSMEM);

    const size_t OUT0 = (size_t)MROWS * NOUTC;

    // Pre-round weights to fp16 (W0, Wl, lin2_w)
    {
        int n4 = WT_W0_ELEMS / 4;
        round_f16_kernel<<<(n4 + 255) / 256, 256>>>(
            (const float4*)W0, (uint2*)pwth, n4);
        n4 = WT_WL_ELEMS / 4;
        round_f16_kernel<<<(n4 + 255) / 256, 256>>>(
            (const float4*)Wl, (uint2*)(pwth + WT_W0_ELEMS), n4);
        n4 = WT_L2_ELEMS / 4;
        round_f16_kernel<<<(n4 + 255) / 256, 256>>>(
            (const float4*)lin2_w, (uint2*)pw_l2, n4);
    }

    // lin1 + relu (exact fp32)
    sgemm_kernel<<<dim3(DDIM / BN, MROWS / BM), 256>>>(
        x, lin1_w, lin1_b, py, MROWS, DDIM, NIN, 1);

    float* cur = py;
    float* nxt = ph;
    for (int li = 0; li < NLAYER; li++) {
        const int   Din = (li == 0) ? DDIM : D2;
        const int   k   = (li == 0) ? 4 : 3;
        const int   Nou = 2 * DDIM * k;
        const float*  g  = (li == 0) ? ln0_g : lnl_g + (size_t)(li - 1) * D2;
        const float*  be = (li == 0) ? ln0_b : lnl_b + (size_t)(li - 1) * D2;
        const __half* W  = (li == 0) ? pwth  : pwth + WT_W0_ELEMS + (size_t)(li - 1) * D2 * 3 * D2;
        const float*  wc = (li == 0) ? wc0   : wcl + (size_t)(li - 1) * 2 * 2 * DDIM;
        const float*  bg = (li == 0) ? b0    : bl  + (size_t)(li - 1) * 2 * 2 * DDIM;

        if (li == 0)
            ln_kernel<1><<<MROWS, 128>>>(
                (const float4*)cur, (const float4*)g, (const float4*)be,
                (uint2*)pxth);
        else
            ln_kernel<2><<<MROWS, 128>>>(
                (const float4*)cur, (const float4*)g, (const float4*)be,
                (uint2*)pxth);

        gemm_f16_kernel<false, false, true>
            <<<dim3(Nou / TBN, MROWS / TBM), 128, TSMEM>>>(
                pxth, W, nullptr, pU, Nou, Din);
        sru_scan_kernel<<<(2 * BATCH * DDIM) / 128, 128>>>(
            pU, pxth, wc, bg, nxt,
            (li == NLAYER - 1) ? pxth : (__half*)nullptr,
            out + OUT0 + (size_t)li * BATCH * D2, k);

        float* t = cur; cur = nxt; nxt = t;
    }

    // lin2 (N=144): last scan wrote fp16 h into pxth
    gemm_f16_kernel<true, true, false>
        <<<dim3((NOUTC + TBN - 1) / TBN, MROWS / TBM), 128, TSMEM>>>(
            pxth, pw_l2, lin2_b, out, NOUTC, D2);
}

// round 14
// speedup vs baseline: 1.2231x; 1.2231x over previous
#include <cuda_runtime.h>
#include <cuda_fp16.h>
#include <math.h>
#include <stdint.h>

// Problem constants
#define LSEQ   512
#define BATCH  32
#define NIN    72
#define DDIM   512
#define NOUTC  144
#define NLAYER 5
#define MROWS  (LSEQ*BATCH)   // 16384
#define D2     (2*DDIM)       // 1024

// Scratch (device globals — no allocation allowed)
__device__ float  g_y [MROWS*D2];
__device__ float  g_xn[MROWS*D2];
__device__ __half g_xth[MROWS*D2];     // fp16 activations (GEMM A operand)
__device__ float  g_U [MROWS*4*D2];
__device__ float  g_h [MROWS*D2];
__device__ __align__(16) __half g_zero8[8] = {};
#define WT_W0_ELEMS (DDIM*4*D2)
#define WT_WL_ELEMS ((NLAYER-1)*D2*3*D2)
#define WT_L2_ELEMS (D2*NOUTC)
__device__ __half g_wth[WT_W0_ELEMS + WT_WL_ELEMS + WT_L2_ELEMS];

// ---------------------------------------------------------------------------
// Helpers
// ---------------------------------------------------------------------------
__device__ __forceinline__ uint32_t smem_u32(const void* p) {
    uint32_t a;
    asm("{ .reg .u64 t; cvta.to.shared.u64 t, %1; cvt.u32.u64 %0, t; }"
        : "=r"(a) : "l"(p));
    return a;
}
__device__ __forceinline__ uint32_t pack_h2(float a, float b) {
    __half2 h = __floats2half2_rn(a, b);
    return *(uint32_t*)&h;
}
__device__ __forceinline__ void cp16(uint32_t s, const void* g) {
    asm volatile("cp.async.cg.shared.global [%0], [%1], 16;" :: "r"(s), "l"(g));
}
// Fast sigmoid: MUFU ex2 + rcp (rel err ~2^-22)
__device__ __forceinline__ float sigmf(float x) {
    float e;
    asm("ex2.approx.ftz.f32 %0, %1;" : "=f"(e) : "f"(-1.44269504f * x));
    float r;
    asm("rcp.approx.ftz.f32 %0, %1;" : "=f"(r) : "f"(1.f + e));
    return r;
}
#define LDSM_X4(r0,r1,r2,r3,addr) \
    asm volatile("ldmatrix.sync.aligned.m8n8.x4.shared.b16 {%0,%1,%2,%3}, [%4];" \
        : "=r"(r0), "=r"(r1), "=r"(r2), "=r"(r3) : "r"(addr))
#define LDSM_X4T(r0,r1,r2,r3,addr) \
    asm volatile("ldmatrix.sync.aligned.m8n8.x4.trans.shared.b16 {%0,%1,%2,%3}, [%4];" \
        : "=r"(r0), "=r"(r1), "=r"(r2), "=r"(r3) : "r"(addr))

// ---------------------------------------------------------------------------
// Round fp32 -> fp16 (vectorized): in float4 x n4 -> out 4 halfs (uint2)
// ---------------------------------------------------------------------------
__global__ __launch_bounds__(256) void round_f16_kernel(
    const float4* __restrict__ in, uint2* __restrict__ out, int n4)
{
    int i = blockIdx.x * blockDim.x + threadIdx.x;
    if (i < n4) {
        float4 v = in[i];
        uint2 t;
        t.x = pack_h2(v.x, v.y);
        t.y = pack_h2(v.z, v.w);
        out[i] = t;
    }
}

// ---------------------------------------------------------------------------
// FP16 tensor-core GEMM: C[M,N](fp32) = A[M,K](fp16) @ B[K,N](fp16).
// Round-5 skeleton: 128x128 CTA tile, BK=32, 128 threads (4 warps, 2x2 grid
// of 64x64 warp tiles), 3-stage cp.async, compute-then-prefetch order.
// Fragments: ldmatrix.x4 (A), ldmatrix.x4.trans (B); mma.m16n8k16.f32.f16.
// M%128==0, K%32==0. GUARD: zero-page OOB B cols + N-guarded epilogue.
// ---------------------------------------------------------------------------
#define TBM 128
#define TBN 128
#define TBK 32
#define ASTR 40                      // halfs per A row (80B, 16B-mult, LDSM-conflict-free)
#define BSTR 136                     // halfs per B row (272B)
#define ABYT (TBM*ASTR*2)            // 10240
#define BBYT (TBK*BSTR*2)            // 8704
#define STG  (ABYT+BBYT)             // 18944
#define TSMEM (3*STG)                // 56832

template<bool GUARD, bool HASBIAS>
__global__ __launch_bounds__(128) void gemm_f16_kernel(
    const __half* __restrict__ A, const __half* __restrict__ B,
    const float* __restrict__ bias, float* __restrict__ C,
    int N, int K)
{
    extern __shared__ char smem[];
    const uint32_t sb = smem_u32(smem);
    const int tid  = threadIdx.x;
    const int w    = tid >> 5;
    const int lane = tid & 31;
    const int wm   = w & 1;        // 0..1  (M)
    const int wn   = w >> 1;       // 0..1  (N)
    const int bm   = blockIdx.y * TBM;
    const int bn   = blockIdx.x * TBN;
    const int l15  = lane & 15;
    const int lhi  = lane >> 4;

    float acc[4][8][4];
    #pragma unroll
    for (int i = 0; i < 4; i++)
        #pragma unroll
        for (int j = 0; j < 8; j++)
            #pragma unroll
            for (int r = 0; r < 4; r++) acc[i][j][r] = 0.f;

    const int nc = K / TBK;

    auto load_chunk = [&](int ch, int s) {
        const int k0 = ch * TBK;
        const uint32_t sA = sb + s * STG;
        const uint32_t sB = sA + ABYT;
        // A: 128 rows x 32 halfs = 512 x 16B chunks, 4/thread
        #pragma unroll
        for (int i = 0; i < 4; i++) {
            int idx = tid + i * 128;
            int row = idx >> 2, q = idx & 3;
            cp16(sA + (row * ASTR + q * 8) * 2,
                 A + (size_t)(bm + row) * K + k0 + q * 8);
        }
        // B: 32 rows x 128 halfs = 512 x 16B chunks, 4/thread
        #pragma unroll
        for (int i = 0; i < 4; i++) {
            int idx = tid + i * 128;
            int row = idx >> 4, q = idx & 15;
            if (GUARD) {
                int gc = bn + q * 8;
                const void* src = (gc < N)
                    ? (const void*)(B + (size_t)(k0 + row) * N + gc)
                    : (const void*)g_zero8;
                cp16(sB + (row * BSTR + q * 8) * 2, src);
            } else {
                cp16(sB + (row * BSTR + q * 8) * 2,
                     B + (size_t)(k0 + row) * N + bn + q * 8);
            }
        }
    };

    // ldmatrix per-lane byte offsets within a stage
    uint32_t aoff[4], boff[4];
    #pragma unroll
    for (int mi = 0; mi < 4; mi++)
        aoff[mi] = ((wm * 64 + mi * 16 + l15) * ASTR + lhi * 8) * 2;
    #pragma unroll
    for (int nj = 0; nj < 4; nj++)
        boff[nj] = (l15 * BSTR + wn * 64 + nj * 16 + lhi * 8) * 2;

    load_chunk(0, 0);
    asm volatile("cp.async.commit_group;" ::: "memory");
    if (nc > 1) load_chunk(1, 1);
    asm volatile("cp.async.commit_group;" ::: "memory");

    for (int ch = 0; ch < nc; ch++) {
        const int s = ch % 3;
        asm volatile("cp.async.wait_group 1;" ::: "memory");
        __syncthreads();

        const uint32_t sA = sb + s * STG;
        const uint32_t sB = sA + ABYT;
        #pragma unroll
        for (int kk = 0; kk < 2; kk++) {
            uint32_t af[4][4], bf[8][2];
            #pragma unroll
            for (int mi = 0; mi < 4; mi++)
                LDSM_X4(af[mi][0], af[mi][1], af[mi][2], af[mi][3],
                        sA + aoff[mi] + kk * 32);          // +16 halfs along k
            #pragma unroll
            for (int nj = 0; nj < 4; nj++)
                LDSM_X4T(bf[2*nj][0], bf[2*nj][1], bf[2*nj+1][0], bf[2*nj+1][1],
                         sB + boff[nj] + kk * 16 * BSTR * 2); // +16 k-rows
            #pragma unroll
            for (int mi = 0; mi < 4; mi++)
                #pragma unroll
                for (int ni = 0; ni < 8; ni++) {
                    asm volatile(
                        "mma.sync.aligned.m16n8k16.row.col.f32.f16.f16.f32 "
                        "{%0,%1,%2,%3}, {%4,%5,%6,%7}, {%8,%9}, {%0,%1,%2,%3};"
                        : "+f"(acc[mi][ni][0]), "+f"(acc[mi][ni][1]),
                          "+f"(acc[mi][ni][2]), "+f"(acc[mi][ni][3])
                        : "r"(af[mi][0]), "r"(af[mi][1]),
                          "r"(af[mi][2]), "r"(af[mi][3]),
                          "r"(bf[ni][0]), "r"(bf[ni][1]));
                }
        }

        if (ch + 2 < nc) load_chunk(ch + 2, (ch + 2) % 3);
        asm volatile("cp.async.commit_group;" ::: "memory");
    }

    // Epilogue (same fragment layout as m16n8k8 path)
    #pragma unroll
    for (int mi = 0; mi < 4; mi++) {
        const size_t r0 = (size_t)bm + wm * 64 + mi * 16 + (lane >> 2);
        #pragma unroll
        for (int ni = 0; ni < 8; ni++) {
            const int colblk = bn + wn * 64 + ni * 8;
            if (GUARD && colblk >= N) continue;
            const int col = colblk + (lane & 3) * 2;
            float v0 = acc[mi][ni][0], v1 = acc[mi][ni][1];
            float v2 = acc[mi][ni][2], v3 = acc[mi][ni][3];
            if (HASBIAS) {
                float b0 = bias[col], b1 = bias[col + 1];
                v0 += b0; v1 += b1; v2 += b0; v3 += b1;
            }
            *(float2*)(C + r0 * N + col)       = make_float2(v0, v1);
            *(float2*)(C + (r0 + 8) * N + col) = make_float2(v2, v3);
        }
    }
}

// ---------------------------------------------------------------------------
// Classic SGEMM (lin1 only: K=72, exact fp32 to preserve error margin)
// ---------------------------------------------------------------------------
#define BM 128
#define BN 128
#define BK 8

__global__ __launch_bounds__(256) void sgemm_kernel(
    const float* __restrict__ A, const float* __restrict__ B,
    const float* __restrict__ bias, float* __restrict__ C,
    int M, int N, int K, int relu)
{
    __shared__ float As[BK][BM];
    __shared__ float Bs[BK][BN];

    const int tid = threadIdx.x;
    const int bm  = blockIdx.y * BM;
    const int bn  = blockIdx.x * BN;
    const int tx  = tid & 15;
    const int ty  = tid >> 4;

    const int arow = tid >> 1;
    const int acol = (tid & 1) * 4;
    const int brow = tid >> 5;
    const int bcol = (tid & 31) * 4;

    float acc[8][8];
    #pragma unroll
    for (int i = 0; i < 8; i++)
        #pragma unroll
        for (int j = 0; j < 8; j++) acc[i][j] = 0.f;

    for (int k0 = 0; k0 < K; k0 += BK) {
        float4 av = *(const float4*)(A + (size_t)(bm + arow) * K + k0 + acol);
        As[acol + 0][arow] = av.x;
        As[acol + 1][arow] = av.y;
        As[acol + 2][arow] = av.z;
        As[acol + 3][arow] = av.w;

        float4 bv = make_float4(0.f, 0.f, 0.f, 0.f);
        int gc = bn + bcol;
        const float* bp = B + (size_t)(k0 + brow) * N;
        if (gc + 3 < N) {
            bv = *(const float4*)(bp + gc);
        } else {
            if (gc     < N) bv.x = bp[gc];
            if (gc + 1 < N) bv.y = bp[gc + 1];
            if (gc + 2 < N) bv.z = bp[gc + 2];
            if (gc + 3 < N) bv.w = bp[gc + 3];
        }
        *(float4*)&Bs[brow][bcol] = bv;

        __syncthreads();

        #pragma unroll
        for (int kk = 0; kk < BK; kk++) {
            float ar[8], br[8];
            *(float4*)&ar[0] = *(const float4*)&As[kk][ty * 8];
            *(float4*)&ar[4] = *(const float4*)&As[kk][ty * 8 + 4];
            *(float4*)&br[0] = *(const float4*)&Bs[kk][tx * 8];
            *(float4*)&br[4] = *(const float4*)&Bs[kk][tx * 8 + 4];
            #pragma unroll
            for (int i = 0; i < 8; i++)
                #pragma unroll
                for (int j = 0; j < 8; j++)
                    acc[i][j] += ar[i] * br[j];
        }
        __syncthreads();
    }

    #pragma unroll
    for (int i = 0; i < 8; i++) {
        int row = bm + ty * 8 + i;
        #pragma unroll
        for (int j = 0; j < 8; j++) {
            int col = bn + tx * 8 + j;
            if (col < N) {
                float v = acc[i][j];
                if (bias) v += bias[col];
                if (relu) v = fmaxf(v, 0.f);
                C[(size_t)row * N + col] = v;
            }
        }
    }
}

// ---------------------------------------------------------------------------
// One-pass LayerNorm, register-resident row. 128 threads, NV4 float4/thread.
// Writes fp16 copy (GEMM A); optional fp32 copy (scan residual, k=3 only).
// ---------------------------------------------------------------------------
template<int NV4, bool WFP32>
__global__ __launch_bounds__(128) void ln_kernel(
    const float4* __restrict__ in, const float4* __restrict__ gw,
    const float4* __restrict__ bw, float4* __restrict__ outp,
    uint2* __restrict__ outh)
{
    const int W4  = NV4 * 128;
    const int row = blockIdx.x;
    const int tid = threadIdx.x;

    float4 v[NV4];
    #pragma unroll
    for (int i = 0; i < NV4; i++)
        v[i] = in[(size_t)row * W4 + tid + i * 128];

    float s = 0.f, s2 = 0.f;
    #pragma unroll
    for (int i = 0; i < NV4; i++) {
        s  += v[i].x + v[i].y + v[i].z + v[i].w;
        s2 += v[i].x * v[i].x + v[i].y * v[i].y
            + v[i].z * v[i].z + v[i].w * v[i].w;
    }

    __shared__ float sh0[4], sh1[4];
    #pragma unroll
    for (int o = 16; o; o >>= 1) {
        s  += __shfl_xor_sync(0xFFFFFFFFu, s,  o);
        s2 += __shfl_xor_sync(0xFFFFFFFFu, s2, o);
    }
    const int wq = tid >> 5, ln = tid & 31;
    if (ln == 0) { sh0[wq] = s; sh1[wq] = s2; }
    __syncthreads();
    s  = sh0[0] + sh0[1] + sh0[2] + sh0[3];
    s2 = sh1[0] + sh1[1] + sh1[2] + sh1[3];

    const float Wf   = (float)(NV4 * 512);
    const float mean = s / Wf;
    const float var  = s2 / Wf - mean * mean;
    const float inv  = rsqrtf(var + 1e-5f);

    #pragma unroll
    for (int i = 0; i < NV4; i++) {
        float4 g = gw[tid + i * 128];
        float4 b = bw[tid + i * 128];
        float4 o;
        o.x = (v[i].x - mean) * inv * g.x + b.x;
        o.y = (v[i].y - mean) * inv * g.y + b.y;
        o.z = (v[i].z - mean) * inv * g.z + b.z;
        o.w = (v[i].w - mean) * inv * g.w + b.w;
        if (WFP32)
            outp[(size_t)row * W4 + tid + i * 128] = o;
        uint2 t;
        t.x = pack_h2(o.x, o.y);
        t.y = pack_h2(o.z, o.w);
        outh[(size_t)row * W4 + tid + i * 128] = t;
    }
}

// ---------------------------------------------------------------------------
// Bidirectional SRU scan, 8-deep register prefetch, fast sigmoid.
// hh != nullptr (last layer): h written as fp16 into hh (feeds lin2 GEMM);
// fp32 h skipped. c_out always exact fp32.
// ---------------------------------------------------------------------------
__global__ __launch_bounds__(128) void sru_scan_kernel(
    const float* __restrict__ U, const float* __restrict__ xn,
    const float* __restrict__ wc, const float* __restrict__ bb,
    float* __restrict__ h, __half* __restrict__ hh,
    float* __restrict__ c_out, int k)
{
    const int idx = blockIdx.x * blockDim.x + threadIdx.x;
    const int d   = idx % DDIM;
    const int b   = (idx / DDIM) % BATCH;
    const int dir = idx / (BATCH * DDIM);

    const float wcf = wc[(0 * 2 + dir) * DDIM + d];
    const float wcr = wc[(1 * 2 + dir) * DDIM + d];
    const float bf  = bb[(0 * 2 + dir) * DDIM + d];
    const float br  = bb[(1 * 2 + dir) * DDIM + d];

    const int hcol = dir * DDIM + d;
    const int t0   = dir ? (LSEQ - 1) : 0;
    float c = 0.f;

    if (k == 4) {
        const float4* U4 = (const float4*)U;
        const long long base = ((long long)t0 * BATCH + b) * D2 + hcol;
        const long long st   = dir ? -(long long)(BATCH * D2) : (long long)(BATCH * D2);
        long long ih = base;

        float4 buf[8];
        #pragma unroll
        for (int j = 0; j < 8; j++) buf[j] = __ldcs(U4 + base + j * st);

        for (int s = 0; s < LSEQ; s += 8) {
            #pragma unroll
            for (int j = 0; j < 8; j++) {
                float4 v = buf[j];
                if (s + 8 + j < LSEQ)
                    buf[j] = __ldcs(U4 + base + (long long)(s + 8 + j) * st);
                float f = sigmf(v.y + wcf * c + bf);
                c = f * c + (1.f - f) * v.x;
                float r = sigmf(v.z + wcr * c + br);
                float hv = r * c + (1.f - r) * v.w;
                if (hh) hh[ih] = __float2half_rn(hv);
                else    h[ih]  = hv;
                ih += st;
            }
        }
    } else {
        const long long baseu = ((long long)t0 * BATCH + b) * (3 * D2) + hcol * 3;
        const long long su    = dir ? -(long long)(BATCH * 3 * D2) : (long long)(BATCH * 3 * D2);
        const long long basex = ((long long)t0 * BATCH + b) * D2 + hcol;
        const long long sx    = dir ? -(long long)(BATCH * D2) : (long long)(BATCH * D2);

        float b0a[8], b1a[8], b2a[8], bra[8];
        #pragma unroll
        for (int j = 0; j < 8; j++) {
            const float* up = U + baseu + j * su;
            b0a[j] = __ldcs(up);
            b1a[j] = __ldcs(up + 1);
            b2a[j] = __ldcs(up + 2);
            bra[j] = __ldcs(xn + basex + j * sx);
        }

        long long ih = basex;
        for (int s = 0; s < LSEQ; s += 8) {
            #pragma unroll
            for (int j = 0; j < 8; j++) {
                float u0 = b0a[j], u1 = b1a[j], u2 = b2a[j], res = bra[j];
                if (s + 8 + j < LSEQ) {
                    const float* up = U + baseu + (long long)(s + 8 + j) * su;
                    b0a[j] = __ldcs(up);
                    b1a[j] = __ldcs(up + 1);
                    b2a[j] = __ldcs(up + 2);
                    bra[j] = __ldcs(xn + basex + (long long)(s + 8 + j) * sx);
                }
                float f = sigmf(u1 + wcf * c + bf);
                c = f * c + (1.f - f) * u0;
                float r = sigmf(u2 + wcr * c + br);
                float hv = r * c + (1.f - r) * res;
                if (hh) hh[ih] = __float2half_rn(hv);
                else    h[ih]  = hv;
                ih += sx;
            }
        }
    }
    c_out[(size_t)b * D2 + hcol] = c;
}

// ---------------------------------------------------------------------------
// Launch
// ---------------------------------------------------------------------------
extern "C" void kernel_launch(void* const* d_in, const int* in_sizes, int n_in,
                              void* d_out, int out_size)
{
    const float* x      = (const float*)d_in[0];
    const float* lin1_w = (const float*)d_in[1];
    const float* lin1_b = (const float*)d_in[2];
    const float* lin2_w = (const float*)d_in[3];
    const float* lin2_b = (const float*)d_in[4];
    const float* W0     = (const float*)d_in[5];
    const float* wc0    = (const float*)d_in[6];
    const float* b0     = (const float*)d_in[7];
    const float* ln0_g  = (const float*)d_in[8];
    const float* ln0_b  = (const float*)d_in[9];
    const float* Wl     = (const float*)d_in[10];
    const float* wcl    = (const float*)d_in[11];
    const float* bl     = (const float*)d_in[12];
    const float* lnl_g  = (const float*)d_in[13];
    const float* lnl_b  = (const float*)d_in[14];
    float* out = (float*)d_out;

    float *py, *pxn, *pU, *ph;
    __half *pxth, *pwth;
    cudaGetSymbolAddress((void**)&py,   g_y);
    cudaGetSymbolAddress((void**)&pxn,  g_xn);
    cudaGetSymbolAddress((void**)&pxth, g_xth);
    cudaGetSymbolAddress((void**)&pU,   g_U);
    cudaGetSymbolAddress((void**)&ph,   g_h);
    cudaGetSymbolAddress((void**)&pwth, g_wth);

    __half* pw_l2 = pwth + WT_W0_ELEMS + WT_WL_ELEMS;

    cudaFuncSetAttribute((const void*)gemm_f16_kernel<false, false>,
                         cudaFuncAttributeMaxDynamicSharedMemorySize, TSMEM);
    cudaFuncSetAttribute((const void*)gemm_f16_kernel<true, true>,
                         cudaFuncAttributeMaxDynamicSharedMemorySize, TSMEM);

    const size_t OUT0 = (size_t)MROWS * NOUTC;

    // Pre-round weights to fp16 (W0, Wl, lin2_w)
    {
        int n4 = WT_W0_ELEMS / 4;
        round_f16_kernel<<<(n4 + 255) / 256, 256>>>(
            (const float4*)W0, (uint2*)pwth, n4);
        n4 = WT_WL_ELEMS / 4;
        round_f16_kernel<<<(n4 + 255) / 256, 256>>>(
            (const float4*)Wl, (uint2*)(pwth + WT_W0_ELEMS), n4);
        n4 = WT_L2_ELEMS / 4;
        round_f16_kernel<<<(n4 + 255) / 256, 256>>>(
            (const float4*)lin2_w, (uint2*)pw_l2, n4);
    }

    // lin1 + relu (exact fp32)
    sgemm_kernel<<<dim3(DDIM / BN, MROWS / BM), 256>>>(
        x, lin1_w, lin1_b, py, MROWS, DDIM, NIN, 1);

    float* cur = py;
    float* nxt = ph;
    for (int li = 0; li < NLAYER; li++) {
        const int   Din = (li == 0) ? DDIM : D2;
        const int   k   = (li == 0) ? 4 : 3;
        const int   Nou = 2 * DDIM * k;
        const float*  g  = (li == 0) ? ln0_g : lnl_g + (size_t)(li - 1) * D2;
        const float*  be = (li == 0) ? ln0_b : lnl_b + (size_t)(li - 1) * D2;
        const __half* W  = (li == 0) ? pwth  : pwth + WT_W0_ELEMS + (size_t)(li - 1) * D2 * 3 * D2;
        const float*  wc = (li == 0) ? wc0   : wcl + (size_t)(li - 1) * 2 * 2 * DDIM;
        const float*  bg = (li == 0) ? b0    : bl  + (size_t)(li - 1) * 2 * 2 * DDIM;

        if (li == 0)   // k=4 scan never reads the fp32 LN copy
            ln_kernel<1, false><<<MROWS, 128>>>(
                (const float4*)cur, (const float4*)g, (const float4*)be,
                (float4*)pxn, (uint2*)pxth);
        else
            ln_kernel<2, true><<<MROWS, 128>>>(
                (const float4*)cur, (const float4*)g, (const float4*)be,
                (float4*)pxn, (uint2*)pxth);

        gemm_f16_kernel<false, false>
            <<<dim3(Nou / TBN, MROWS / TBM), 128, TSMEM>>>(
                pxth, W, nullptr, pU, Nou, Din);
        sru_scan_kernel<<<(2 * BATCH * DDIM) / 128, 128>>>(
            pU, pxn, wc, bg, nxt,
            (li == NLAYER - 1) ? pxth : (__half*)nullptr,
            out + OUT0 + (size_t)li * BATCH * D2, k);

        float* t = cur; cur = nxt; nxt = t;
    }

    // lin2 (N=144): last scan wrote fp16 h into pxth
    gemm_f16_kernel<true, true>
        <<<dim3((NOUTC + TBN - 1) / TBN, MROWS / TBM), 128, TSMEM>>>(
            pxth, pw_l2, lin2_b, out, NOUTC, D2);
}

// round 15
// speedup vs baseline: 1.2771x; 1.0441x over previous
#include <cuda_runtime.h>
#include <cuda_fp16.h>
#include <math.h>
#include <stdint.h>

// Problem constants
#define LSEQ   512
#define BATCH  32
#define NIN    72
#define DDIM   512
#define NOUTC  144
#define NLAYER 5
#define MROWS  (LSEQ*BATCH)   // 16384
#define D2     (2*DDIM)       // 1024

// Scratch (device globals — no allocation allowed)
__device__ float  g_y [MROWS*D2];
__device__ float  g_xn[MROWS*D2];
__device__ __half g_xth[MROWS*D2];     // fp16 activations (GEMM A operand)
__device__ float  g_U [MROWS*4*D2];
__device__ float  g_h [MROWS*D2];
__device__ __align__(16) __half g_zero8[8] = {};
#define WT_W0_ELEMS (DDIM*4*D2)
#define WT_WL_ELEMS ((NLAYER-1)*D2*3*D2)
#define WT_L2_ELEMS (D2*NOUTC)
__device__ __half g_wth[WT_W0_ELEMS + WT_WL_ELEMS + WT_L2_ELEMS];

// ---------------------------------------------------------------------------
// Helpers
// ---------------------------------------------------------------------------
__device__ __forceinline__ uint32_t smem_u32(const void* p) {
    uint32_t a;
    asm("{ .reg .u64 t; cvta.to.shared.u64 t, %1; cvt.u32.u64 %0, t; }"
        : "=r"(a) : "l"(p));
    return a;
}
__device__ __forceinline__ uint32_t pack_h2(float a, float b) {
    __half2 h = __floats2half2_rn(a, b);
    return *(uint32_t*)&h;
}
__device__ __forceinline__ void cp16(uint32_t s, const void* g) {
    asm volatile("cp.async.cg.shared.global [%0], [%1], 16;" :: "r"(s), "l"(g));
}
// Fast sigmoid: MUFU ex2 + rcp (rel err ~2^-22)
__device__ __forceinline__ float sigmf(float x) {
    float e;
    asm("ex2.approx.ftz.f32 %0, %1;" : "=f"(e) : "f"(-1.44269504f * x));
    float r;
    asm("rcp.approx.ftz.f32 %0, %1;" : "=f"(r) : "f"(1.f + e));
    return r;
}
#define LDSM_X4(r0,r1,r2,r3,addr) \
    asm volatile("ldmatrix.sync.aligned.m8n8.x4.shared.b16 {%0,%1,%2,%3}, [%4];" \
        : "=r"(r0), "=r"(r1), "=r"(r2), "=r"(r3) : "r"(addr))
#define LDSM_X4T(r0,r1,r2,r3,addr) \
    asm volatile("ldmatrix.sync.aligned.m8n8.x4.trans.shared.b16 {%0,%1,%2,%3}, [%4];" \
        : "=r"(r0), "=r"(r1), "=r"(r2), "=r"(r3) : "r"(addr))

// ---------------------------------------------------------------------------
// Round fp32 -> fp16 (vectorized)
// ---------------------------------------------------------------------------
__global__ __launch_bounds__(256) void round_f16_kernel(
    const float4* __restrict__ in, uint2* __restrict__ out, int n4)
{
    int i = blockIdx.x * blockDim.x + threadIdx.x;
    if (i < n4) {
        float4 v = in[i];
        uint2 t;
        t.x = pack_h2(v.x, v.y);
        t.y = pack_h2(v.z, v.w);
        out[i] = t;
    }
}

// ---------------------------------------------------------------------------
// FP16 tensor-core GEMM — round-11 validated config, FROZEN.
// 128x128 CTA tile, BK=32, 128 threads (4 warps, 2x2 grid of 64x64 warp
// tiles), 3-stage cp.async, compute-then-prefetch order, 2 CTAs/SM.
// ---------------------------------------------------------------------------
#define TBM 128
#define TBN 128
#define TBK 32
#define ASTR 40
#define BSTR 136
#define ABYT (TBM*ASTR*2)            // 10240
#define BBYT (TBK*BSTR*2)            // 8704
#define STG  (ABYT+BBYT)             // 18944
#define TSMEM (3*STG)                // 56832

template<bool GUARD, bool HASBIAS>
__global__ __launch_bounds__(128) void gemm_f16_kernel(
    const __half* __restrict__ A, const __half* __restrict__ B,
    const float* __restrict__ bias, float* __restrict__ C,
    int N, int K)
{
    extern __shared__ char smem[];
    const uint32_t sb = smem_u32(smem);
    const int tid  = threadIdx.x;
    const int w    = tid >> 5;
    const int lane = tid & 31;
    const int wm   = w & 1;
    const int wn   = w >> 1;
    const int bm   = blockIdx.y * TBM;
    const int bn   = blockIdx.x * TBN;
    const int l15  = lane & 15;
    const int lhi  = lane >> 4;

    float acc[4][8][4];
    #pragma unroll
    for (int i = 0; i < 4; i++)
        #pragma unroll
        for (int j = 0; j < 8; j++)
            #pragma unroll
            for (int r = 0; r < 4; r++) acc[i][j][r] = 0.f;

    const int nc = K / TBK;

    auto load_chunk = [&](int ch, int s) {
        const int k0 = ch * TBK;
        const uint32_t sA = sb + s * STG;
        const uint32_t sB = sA + ABYT;
        #pragma unroll
        for (int i = 0; i < 4; i++) {
            int idx = tid + i * 128;
            int row = idx >> 2, q = idx & 3;
            cp16(sA + (row * ASTR + q * 8) * 2,
                 A + (size_t)(bm + row) * K + k0 + q * 8);
        }
        #pragma unroll
        for (int i = 0; i < 4; i++) {
            int idx = tid + i * 128;
            int row = idx >> 4, q = idx & 15;
            if (GUARD) {
                int gc = bn + q * 8;
                const void* src = (gc < N)
                    ? (const void*)(B + (size_t)(k0 + row) * N + gc)
                    : (const void*)g_zero8;
                cp16(sB + (row * BSTR + q * 8) * 2, src);
            } else {
                cp16(sB + (row * BSTR + q * 8) * 2,
                     B + (size_t)(k0 + row) * N + bn + q * 8);
            }
        }
    };

    uint32_t aoff[4], boff[4];
    #pragma unroll
    for (int mi = 0; mi < 4; mi++)
        aoff[mi] = ((wm * 64 + mi * 16 + l15) * ASTR + lhi * 8) * 2;
    #pragma unroll
    for (int nj = 0; nj < 4; nj++)
        boff[nj] = (l15 * BSTR + wn * 64 + nj * 16 + lhi * 8) * 2;

    load_chunk(0, 0);
    asm volatile("cp.async.commit_group;" ::: "memory");
    if (nc > 1) load_chunk(1, 1);
    asm volatile("cp.async.commit_group;" ::: "memory");

    for (int ch = 0; ch < nc; ch++) {
        const int s = ch % 3;
        asm volatile("cp.async.wait_group 1;" ::: "memory");
        __syncthreads();

        const uint32_t sA = sb + s * STG;
        const uint32_t sB = sA + ABYT;
        #pragma unroll
        for (int kk = 0; kk < 2; kk++) {
            uint32_t af[4][4], bf[8][2];
            #pragma unroll
            for (int mi = 0; mi < 4; mi++)
                LDSM_X4(af[mi][0], af[mi][1], af[mi][2], af[mi][3],
                        sA + aoff[mi] + kk * 32);
            #pragma unroll
            for (int nj = 0; nj < 4; nj++)
                LDSM_X4T(bf[2*nj][0], bf[2*nj][1], bf[2*nj+1][0], bf[2*nj+1][1],
                         sB + boff[nj] + kk * 16 * BSTR * 2);
            #pragma unroll
            for (int mi = 0; mi < 4; mi++)
                #pragma unroll
                for (int ni = 0; ni < 8; ni++) {
                    asm volatile(
                        "mma.sync.aligned.m16n8k16.row.col.f32.f16.f16.f32 "
                        "{%0,%1,%2,%3}, {%4,%5,%6,%7}, {%8,%9}, {%0,%1,%2,%3};"
                        : "+f"(acc[mi][ni][0]), "+f"(acc[mi][ni][1]),
                          "+f"(acc[mi][ni][2]), "+f"(acc[mi][ni][3])
                        : "r"(af[mi][0]), "r"(af[mi][1]),
                          "r"(af[mi][2]), "r"(af[mi][3]),
                          "r"(bf[ni][0]), "r"(bf[ni][1]));
                }
        }

        if (ch + 2 < nc) load_chunk(ch + 2, (ch + 2) % 3);
        asm volatile("cp.async.commit_group;" ::: "memory");
    }

    // Epilogue
    #pragma unroll
    for (int mi = 0; mi < 4; mi++) {
        const size_t r0 = (size_t)bm + wm * 64 + mi * 16 + (lane >> 2);
        #pragma unroll
        for (int ni = 0; ni < 8; ni++) {
            const int colblk = bn + wn * 64 + ni * 8;
            if (GUARD && colblk >= N) continue;
            const int col = colblk + (lane & 3) * 2;
            float v0 = acc[mi][ni][0], v1 = acc[mi][ni][1];
            float v2 = acc[mi][ni][2], v3 = acc[mi][ni][3];
            if (HASBIAS) {
                float b0 = bias[col], b1 = bias[col + 1];
                v0 += b0; v1 += b1; v2 += b0; v3 += b1;
            }
            *(float2*)(C + r0 * N + col)       = make_float2(v0, v1);
            *(float2*)(C + (r0 + 8) * N + col) = make_float2(v2, v3);
        }
    }
}

// ---------------------------------------------------------------------------
// Classic SGEMM (lin1 only: K=72, exact fp32)
// ---------------------------------------------------------------------------
#define BM 128
#define BN 128
#define BK 8

__global__ __launch_bounds__(256) void sgemm_kernel(
    const float* __restrict__ A, const float* __restrict__ B,
    const float* __restrict__ bias, float* __restrict__ C,
    int M, int N, int K, int relu)
{
    __shared__ float As[BK][BM];
    __shared__ float Bs[BK][BN];

    const int tid = threadIdx.x;
    const int bm  = blockIdx.y * BM;
    const int bn  = blockIdx.x * BN;
    const int tx  = tid & 15;
    const int ty  = tid >> 4;

    const int arow = tid >> 1;
    const int acol = (tid & 1) * 4;
    const int brow = tid >> 5;
    const int bcol = (tid & 31) * 4;

    float acc[8][8];
    #pragma unroll
    for (int i = 0; i < 8; i++)
        #pragma unroll
        for (int j = 0; j < 8; j++) acc[i][j] = 0.f;

    for (int k0 = 0; k0 < K; k0 += BK) {
        float4 av = *(const float4*)(A + (size_t)(bm + arow) * K + k0 + acol);
        As[acol + 0][arow] = av.x;
        As[acol + 1][arow] = av.y;
        As[acol + 2][arow] = av.z;
        As[acol + 3][arow] = av.w;

        float4 bv = make_float4(0.f, 0.f, 0.f, 0.f);
        int gc = bn + bcol;
        const float* bp = B + (size_t)(k0 + brow) * N;
        if (gc + 3 < N) {
            bv = *(const float4*)(bp + gc);
        } else {
            if (gc     < N) bv.x = bp[gc];
            if (gc + 1 < N) bv.y = bp[gc + 1];
            if (gc + 2 < N) bv.z = bp[gc + 2];
            if (gc + 3 < N) bv.w = bp[gc + 3];
        }
        *(float4*)&Bs[brow][bcol] = bv;

        __syncthreads();

        #pragma unroll
        for (int kk = 0; kk < BK; kk++) {
            float ar[8], br[8];
            *(float4*)&ar[0] = *(const float4*)&As[kk][ty * 8];
            *(float4*)&ar[4] = *(const float4*)&As[kk][ty * 8 + 4];
            *(float4*)&br[0] = *(const float4*)&Bs[kk][tx * 8];
            *(float4*)&br[4] = *(const float4*)&Bs[kk][tx * 8 + 4];
            #pragma unroll
            for (int i = 0; i < 8; i++)
                #pragma unroll
                for (int j = 0; j < 8; j++)
                    acc[i][j] += ar[i] * br[j];
        }
        __syncthreads();
    }

    #pragma unroll
    for (int i = 0; i < 8; i++) {
        int row = bm + ty * 8 + i;
        #pragma unroll
        for (int j = 0; j < 8; j++) {
            int col = bn + tx * 8 + j;
            if (col < N) {
                float v = acc[i][j];
                if (bias) v += bias[col];
                if (relu) v = fmaxf(v, 0.f);
                C[(size_t)row * N + col] = v;
            }
        }
    }
}

// ---------------------------------------------------------------------------
// One-pass LayerNorm, register-resident row. 128 threads, NV4 float4/thread.
// ---------------------------------------------------------------------------
template<int NV4, bool WFP32>
__global__ __launch_bounds__(128) void ln_kernel(
    const float4* __restrict__ in, const float4* __restrict__ gw,
    const float4* __restrict__ bw, float4* __restrict__ outp,
    uint2* __restrict__ outh)
{
    const int W4  = NV4 * 128;
    const int row = blockIdx.x;
    const int tid = threadIdx.x;

    float4 v[NV4];
    #pragma unroll
    for (int i = 0; i < NV4; i++)
        v[i] = in[(size_t)row * W4 + tid + i * 128];

    float s = 0.f, s2 = 0.f;
    #pragma unroll
    for (int i = 0; i < NV4; i++) {
        s  += v[i].x + v[i].y + v[i].z + v[i].w;
        s2 += v[i].x * v[i].x + v[i].y * v[i].y
            + v[i].z * v[i].z + v[i].w * v[i].w;
    }

    __shared__ float sh0[4], sh1[4];
    #pragma unroll
    for (int o = 16; o; o >>= 1) {
        s  += __shfl_xor_sync(0xFFFFFFFFu, s,  o);
        s2 += __shfl_xor_sync(0xFFFFFFFFu, s2, o);
    }
    const int wq = tid >> 5, ln = tid & 31;
    if (ln == 0) { sh0[wq] = s; sh1[wq] = s2; }
    __syncthreads();
    s  = sh0[0] + sh0[1] + sh0[2] + sh0[3];
    s2 = sh1[0] + sh1[1] + sh1[2] + sh1[3];

    const float Wf   = (float)(NV4 * 512);
    const float mean = s / Wf;
    const float var  = s2 / Wf - mean * mean;
    const float inv  = rsqrtf(var + 1e-5f);

    #pragma unroll
    for (int i = 0; i < NV4; i++) {
        float4 g = gw[tid + i * 128];
        float4 b = bw[tid + i * 128];
        float4 o;
        o.x = (v[i].x - mean) * inv * g.x + b.x;
        o.y = (v[i].y - mean) * inv * g.y + b.y;
        o.z = (v[i].z - mean) * inv * g.z + b.z;
        o.w = (v[i].w - mean) * inv * g.w + b.w;
        if (WFP32)
            outp[(size_t)row * W4 + tid + i * 128] = o;
        uint2 t;
        t.x = pack_h2(o.x, o.y);
        t.y = pack_h2(o.z, o.w);
        outh[(size_t)row * W4 + tid + i * 128] = t;
    }
}

// ---------------------------------------------------------------------------
// Bidirectional SRU scan, 16-deep register prefetch ring (static indices),
// fast sigmoid. hh != nullptr (last layer): h written fp16 into hh.
// c_out always exact fp32. Arithmetic order identical to the 8-deep version.
// ---------------------------------------------------------------------------
#define PF 16

__global__ __launch_bounds__(128) void sru_scan_kernel(
    const float* __restrict__ U, const float* __restrict__ xn,
    const float* __restrict__ wc, const float* __restrict__ bb,
    float* __restrict__ h, __half* __restrict__ hh,
    float* __restrict__ c_out, int k)
{
    const int idx = blockIdx.x * blockDim.x + threadIdx.x;
    const int d   = idx % DDIM;
    const int b   = (idx / DDIM) % BATCH;
    const int dir = idx / (BATCH * DDIM);

    const float wcf = wc[(0 * 2 + dir) * DDIM + d];
    const float wcr = wc[(1 * 2 + dir) * DDIM + d];
    const float bf  = bb[(0 * 2 + dir) * DDIM + d];
    const float br  = bb[(1 * 2 + dir) * DDIM + d];

    const int hcol = dir * DDIM + d;
    const int t0   = dir ? (LSEQ - 1) : 0;
    float c = 0.f;

    if (k == 4) {
        const float4* U4 = (const float4*)U;
        const long long base = ((long long)t0 * BATCH + b) * D2 + hcol;
        const long long st   = dir ? -(long long)(BATCH * D2) : (long long)(BATCH * D2);
        long long ih = base;

        float4 buf[PF];
        #pragma unroll
        for (int j = 0; j < PF; j++) buf[j] = __ldcs(U4 + base + j * st);

        for (int s = 0; s < LSEQ; s += PF) {
            #pragma unroll
            for (int j = 0; j < PF; j++) {
                float4 v = buf[j];
                if (s + PF + j < LSEQ)
                    buf[j] = __ldcs(U4 + base + (long long)(s + PF + j) * st);
                float f = sigmf(v.y + wcf * c + bf);
                c = f * c + (1.f - f) * v.x;
                float r = sigmf(v.z + wcr * c + br);
                float hv = r * c + (1.f - r) * v.w;
                if (hh) hh[ih] = __float2half_rn(hv);
                else    h[ih]  = hv;
                ih += st;
            }
        }
    } else {
        const long long baseu = ((long long)t0 * BATCH + b) * (3 * D2) + hcol * 3;
        const long long su    = dir ? -(long long)(BATCH * 3 * D2) : (long long)(BATCH * 3 * D2);
        const long long basex = ((long long)t0 * BATCH + b) * D2 + hcol;
        const long long sx    = dir ? -(long long)(BATCH * D2) : (long long)(BATCH * D2);

        float b0a[PF], b1a[PF], b2a[PF], bra[PF];
        #pragma unroll
        for (int j = 0; j < PF; j++) {
            const float* up = U + baseu + j * su;
            b0a[j] = __ldcs(up);
            b1a[j] = __ldcs(up + 1);
            b2a[j] = __ldcs(up + 2);
            bra[j] = __ldcs(xn + basex + j * sx);
        }

        long long ih = basex;
        for (int s = 0; s < LSEQ; s += PF) {
            #pragma unroll
            for (int j = 0; j < PF; j++) {
                float u0 = b0a[j], u1 = b1a[j], u2 = b2a[j], res = bra[j];
                if (s + PF + j < LSEQ) {
                    const float* up = U + baseu + (long long)(s + PF + j) * su;
                    b0a[j] = __ldcs(up);
                    b1a[j] = __ldcs(up + 1);
                    b2a[j] = __ldcs(up + 2);
                    bra[j] = __ldcs(xn + basex + (long long)(s + PF + j) * sx);
                }
                float f = sigmf(u1 + wcf * c + bf);
                c = f * c + (1.f - f) * u0;
                float r = sigmf(u2 + wcr * c + br);
                float hv = r * c + (1.f - r) * res;
                if (hh) hh[ih] = __float2half_rn(hv);
                else    h[ih]  = hv;
                ih += sx;
            }
        }
    }
    c_out[(size_t)b * D2 + hcol] = c;
}

// ---------------------------------------------------------------------------
// Launch
// ---------------------------------------------------------------------------
extern "C" void kernel_launch(void* const* d_in, const int* in_sizes, int n_in,
                              void* d_out, int out_size)
{
    const float* x      = (const float*)d_in[0];
    const float* lin1_w = (const float*)d_in[1];
    const float* lin1_b = (const float*)d_in[2];
    const float* lin2_w = (const float*)d_in[3];
    const float* lin2_b = (const float*)d_in[4];
    const float* W0     = (const float*)d_in[5];
    const float* wc0    = (const float*)d_in[6];
    const float* b0     = (const float*)d_in[7];
    const float* ln0_g  = (const float*)d_in[8];
    const float* ln0_b  = (const float*)d_in[9];
    const float* Wl     = (const float*)d_in[10];
    const float* wcl    = (const float*)d_in[11];
    const float* bl     = (const float*)d_in[12];
    const float* lnl_g  = (const float*)d_in[13];
    const float* lnl_b  = (const float*)d_in[14];
    float* out = (float*)d_out;

    float *py, *pxn, *pU, *ph;
    __half *pxth, *pwth;
    cudaGetSymbolAddress((void**)&py,   g_y);
    cudaGetSymbolAddress((void**)&pxn,  g_xn);
    cudaGetSymbolAddress((void**)&pxth, g_xth);
    cudaGetSymbolAddress((void**)&pU,   g_U);
    cudaGetSymbolAddress((void**)&ph,   g_h);
    cudaGetSymbolAddress((void**)&pwth, g_wth);

    __half* pw_l2 = pwth + WT_W0_ELEMS + WT_WL_ELEMS;

    cudaFuncSetAttribute((const void*)gemm_f16_kernel<false, false>,
                         cudaFuncAttributeMaxDynamicSharedMemorySize, TSMEM);
    cudaFuncSetAttribute((const void*)gemm_f16_kernel<true, true>,
                         cudaFuncAttributeMaxDynamicSharedMemorySize, TSMEM);

    const size_t OUT0 = (size_t)MROWS * NOUTC;

    // Pre-round weights to fp16 (W0, Wl, lin2_w)
    {
        int n4 = WT_W0_ELEMS / 4;
        round_f16_kernel<<<(n4 + 255) / 256, 256>>>(
            (const float4*)W0, (uint2*)pwth, n4);
        n4 = WT_WL_ELEMS / 4;
        round_f16_kernel<<<(n4 + 255) / 256, 256>>>(
            (const float4*)Wl, (uint2*)(pwth + WT_W0_ELEMS), n4);
        n4 = WT_L2_ELEMS / 4;
        round_f16_kernel<<<(n4 + 255) / 256, 256>>>(
            (const float4*)lin2_w, (uint2*)pw_l2, n4);
    }

    // lin1 + relu (exact fp32)
    sgemm_kernel<<<dim3(DDIM / BN, MROWS / BM), 256>>>(
        x, lin1_w, lin1_b, py, MROWS, DDIM, NIN, 1);

    float* cur = py;
    float* nxt = ph;
    for (int li = 0; li < NLAYER; li++) {
        const int   Din = (li == 0) ? DDIM : D2;
        const int   k   = (li == 0) ? 4 : 3;
        const int   Nou = 2 * DDIM * k;
        const float*  g  = (li == 0) ? ln0_g : lnl_g + (size_t)(li - 1) * D2;
        const float*  be = (li == 0) ? ln0_b : lnl_b + (size_t)(li - 1) * D2;
        const __half* W  = (li == 0) ? pwth  : pwth + WT_W0_ELEMS + (size_t)(li - 1) * D2 * 3 * D2;
        const float*  wc = (li == 0) ? wc0   : wcl + (size_t)(li - 1) * 2 * 2 * DDIM;
        const float*  bg = (li == 0) ? b0    : bl  + (size_t)(li - 1) * 2 * 2 * DDIM;

        if (li == 0)   // k=4 scan never reads the fp32 LN copy
            ln_kernel<1, false><<<MROWS, 128>>>(
                (const float4*)cur, (const float4*)g, (const float4*)be,
                (float4*)pxn, (uint2*)pxth);
        else
            ln_kernel<2, true><<<MROWS, 128>>>(
                (const float4*)cur, (const float4*)g, (const float4*)be,
                (float4*)pxn, (uint2*)pxth);

        gemm_f16_kernel<false, false>
            <<<dim3(Nou / TBN, MROWS / TBM), 128, TSMEM>>>(
                pxth, W, nullptr, pU, Nou, Din);
        sru_scan_kernel<<<(2 * BATCH * DDIM) / 128, 128>>>(
            pU, pxn, wc, bg, nxt,
            (li == NLAYER - 1) ? pxth : (__half*)nullptr,
            out + OUT0 + (size_t)li * BATCH * D2, k);

        float* t = cur; cur = nxt; nxt = t;
    }

    // lin2 (N=144): last scan wrote fp16 h into pxth
    gemm_f16_kernel<true, true>
        <<<dim3((NOUTC + TBN - 1) / TBN, MROWS / TBM), 128, TSMEM>>>(
            pxth, pw_l2, lin2_b, out, NOUTC, D2);
}